// round 13
// baseline (speedup 1.0000x reference)
#include <cuda_runtime.h>
#include <cstdint>

#define BATCH 16
#define CCH   512
#define HW    4096
#define NGRP  32
#define CPG   16
#define NH    8
#define HD    64
#define EPSV  1e-5f
#define WBSZ  (8 * 64 * 32 * 20)     // 512-row weight blob words
#define GSQ   (CCH * CCH)            // 262144
#define KSPL  2                      // gram split-K

// ---------------- scratch ----------------
__device__ uint32_t g_xn  [(size_t)BATCH * CCH * HW];   // tf32 bits [b][c][n]
__device__ uint32_t g_G   [(size_t)BATCH * GSQ];        // Gram tf32 [b][c1][c2]
__device__ float    g_gp  [(size_t)KSPL * BATCH * 10 * 16384]; // gram split-K partials
__device__ float    g_T   [(size_t)BATCH * GSQ];        // Wq@G fp32 [b][o][c2]
__device__ uint32_t g_V1  [(size_t)BATCH * GSQ];        // P·Wv tf32 [b][c1][k]
__device__ float    g_M   [(size_t)BATCH * GSQ];        // Wp@V1 fp32
__device__ uint32_t g_mblob[(size_t)BATCH * WBSZ];
__device__ uint32_t g_wtq8[WBSZ];                       // Wq blob (w_qkv rows 0..511)
__device__ uint32_t g_wtp [WBSZ];                       // Wp blob
__device__ float g_sc[BATCH * CCH], g_bs[BATCH * CCH];  // GN fused scale/bias
__device__ float g_r  [BATCH * CCH];                    // xn row sums
__device__ float g_rqk[BATCH * 1024];                   // W_{q,k} @ r
__device__ float g_ssp[(size_t)BATCH * NH * 4 * HD * HD]; // S split-K partials
__device__ float g_Pm [(size_t)BATCH * NH * HD * HD];   // softmaxed P
__device__ float g_pvec[BATCH * CCH];
__device__ float g_cvec[BATCH * CCH];

// ---------------- helpers ----------------
__device__ __forceinline__ uint32_t f2t(float f) {
    uint32_t u; asm("cvt.rna.tf32.f32 %0, %1;" : "=r"(u) : "f"(f)); return u;
}
__device__ __forceinline__ uint32_t sptr(const void* p) {
    uint32_t a;
    asm("{ .reg .u64 t; cvta.to.shared.u64 t, %1; cvt.u32.u64 %0, t; }" : "=r"(a) : "l"(p));
    return a;
}
__device__ __forceinline__ void cpa16(uint32_t dst, const void* src) {
    asm volatile("cp.async.cg.shared.global [%0], [%1], 16;" :: "r"(dst), "l"(src));
}
__device__ __forceinline__ void cpa_commit() { asm volatile("cp.async.commit_group;" ::: "memory"); }
__device__ __forceinline__ void cpa_wait2()  { asm volatile("cp.async.wait_group 2;" ::: "memory"); }
#define MMA_TF32(acc, a4, b0, b1) \
    asm volatile("mma.sync.aligned.m16n8k8.row.col.f32.tf32.tf32.f32 " \
        "{%0,%1,%2,%3}, {%4,%5,%6,%7}, {%8,%9}, {%0,%1,%2,%3};" \
        : "+f"((acc)[0]), "+f"((acc)[1]), "+f"((acc)[2]), "+f"((acc)[3]) \
        : "r"((a4).x), "r"((a4).y), "r"((a4).z), "r"((a4).w), "r"(b0), "r"(b1))

// ---------------- K0: weight blobs ----------------
__global__ __launch_bounds__(256) void wt_kernel(
    const float* __restrict__ Wq, const float* __restrict__ Wp)
{
    int idx = blockIdx.x * 256 + threadIdx.x;   // 32768
    const float* W; uint32_t* blob; int e;
    if (idx < 16384) { W = Wq; blob = g_wtq8; e = idx; }
    else             { W = Wp; blob = g_wtp;  e = idx - 16384; }
    int lane = e & 31, k8 = (e >> 5) & 63, m64 = e >> 11;
    int t4 = lane & 3, g4 = lane >> 2;
    uint32_t out[16];
    #pragma unroll
    for (int w = 0; w < 16; w++) {
        int mf = w >> 2, j = w & 3;
        int kk = k8 * 8 + t4 + ((j >> 1) << 2);
        int oo = m64 * 64 + mf * 16 + g4 + ((j & 1) << 3);
        out[w] = f2t(W[(size_t)oo * CCH + kk]);
    }
    uint32_t* dst = blob + (size_t)e * 20;
    #pragma unroll
    for (int q = 0; q < 4; q++)
        *(uint4*)(dst + q * 4) = make_uint4(out[q*4], out[q*4+1], out[q*4+2], out[q*4+3]);
}

// ---------------- K1: GroupNorm FUSED: stats + normalize + row sums --------
__global__ __launch_bounds__(256) void gn_kernel(
    const float* __restrict__ x, const float* __restrict__ gamma,
    const float* __restrict__ beta)
{
    int bg = blockIdx.x;
    int b = bg / NGRP, g = bg % NGRP;
    const float* xp = x + ((size_t)b * CCH + (size_t)g * CPG) * HW;
    int tid = threadIdx.x;
    int warp = tid >> 5, lane = tid & 31;

    float s = 0.f, ss = 0.f;
    const float4* xp4 = (const float4*)xp;
    for (int i = tid; i < (CPG * HW) / 4; i += 256) {
        float4 v = xp4[i];
        s  += v.x + v.y + v.z + v.w;
        ss += v.x*v.x + v.y*v.y + v.z*v.z + v.w*v.w;
    }
    __shared__ float sh_s[256], sh_ss[256];
    __shared__ float sc16[CPG], bs16[CPG];
    sh_s[tid] = s; sh_ss[tid] = ss;
    __syncthreads();
    for (int off = 128; off > 0; off >>= 1) {
        if (tid < off) { sh_s[tid] += sh_s[tid+off]; sh_ss[tid] += sh_ss[tid+off]; }
        __syncthreads();
    }
    if (tid < CPG) {
        const float inv_n = 1.0f / (float)(CPG * HW);
        float mean = sh_s[0] * inv_n;
        float var  = sh_ss[0] * inv_n - mean * mean;
        float inv  = rsqrtf(var + EPSV);
        int c = g * CPG + tid;
        float ga = gamma[c], be = beta[c];
        float scv = ga * inv, bsv = be - mean * inv * ga;
        sc16[tid] = scv; bs16[tid] = bsv;
        g_sc[b * CCH + c] = scv;          // exported for XNORM final GEMM
        g_bs[b * CCH + c] = bsv;
    }
    __syncthreads();

    #pragma unroll
    for (int half = 0; half < 2; half++) {
        int c = warp * 2 + half;
        float sc = sc16[c], bs = bs16[c];
        const float4* src = (const float4*)(xp + (size_t)c * HW);
        uint4* dst = (uint4*)(g_xn + ((size_t)(b * CCH + g * CPG + c)) * HW);
        float sum = 0.f;
        for (int i = lane; i < HW / 4; i += 32) {
            float4 v = src[i];
            uint4 u;
            u.x = f2t(fmaf(v.x, sc, bs));
            u.y = f2t(fmaf(v.y, sc, bs));
            u.z = f2t(fmaf(v.z, sc, bs));
            u.w = f2t(fmaf(v.w, sc, bs));
            dst[i] = u;
            sum += __uint_as_float(u.x) + __uint_as_float(u.y)
                 + __uint_as_float(u.z) + __uint_as_float(u.w);
        }
        #pragma unroll
        for (int off = 16; off > 0; off >>= 1)
            sum += __shfl_xor_sync(0xFFFFFFFF, sum, off);
        if (lane == 0)
            g_r[b * CCH + g * CPG + c] = sum;
    }
}

// ---------------- K3: Gram split-K partials (reads g_xn) ----------
__device__ const int TRI_I[10] = {0,1,1,2,2,2,3,3,3,3};
__device__ const int TRI_J[10] = {0,0,1,0,1,2,0,1,2,3};
#define GRSTG  (2 * 128 * 20)        // 5120 words per slot
#define GRSMEM (4 * GRSTG * 4)       // 81920 bytes

__global__ __launch_bounds__(256, 2) void gram_kernel()
{
    extern __shared__ uint32_t sm[];
    const int tid = threadIdx.x, lane = tid & 31, wid = tid >> 5;
    const int ti = blockIdx.x, b = blockIdx.y, ksp = blockIdx.z;
    const int m0 = TRI_I[ti] * 128, n0 = TRI_J[ti] * 128;
    const uint32_t* Xp = g_xn + (size_t)b * CCH * HW;
    const uint32_t smb = sptr(sm);
    const int wm = wid >> 2, wn = wid & 3;
    const int mb = wm * 64, nb = wn * 32;
    const int g4 = lane >> 2, t4 = lane & 3;
    const int kbase = ksp * (HW / KSPL);   // 2048

    auto issue = [&](int s) {
        const int slot = s & 3;
        const uint32_t ad = smb + (uint32_t)slot * GRSTG * 4;
        const uint32_t bd = ad + 128 * 20 * 4;
        const int k0 = kbase + s * 16;
        #pragma unroll
        for (int i = 0; i < 2; i++) {
            int ch = tid + i * 256;
            int row = ch >> 2, kq = ch & 3;
            cpa16(ad + (uint32_t)(row * 20 + kq * 4) * 4,
                  Xp + (size_t)(m0 + row) * HW + k0 + kq * 4);
            cpa16(bd + (uint32_t)(row * 20 + kq * 4) * 4,
                  Xp + (size_t)(n0 + row) * HW + k0 + kq * 4);
        }
        cpa_commit();
    };

    float acc[4][4][4];
    #pragma unroll
    for (int i = 0; i < 4; i++)
        #pragma unroll
        for (int j = 0; j < 4; j++)
            #pragma unroll
            for (int r = 0; r < 4; r++) acc[i][j][r] = 0.f;

    issue(0); issue(1);
    const int NS = (HW / KSPL) / 16;   // 128
    #pragma unroll 1
    for (int s = 0; s < NS; s++) {
        if (s + 2 < NS) issue(s + 2); else cpa_commit();
        cpa_wait2();
        __syncthreads();
        const uint32_t* as = sm + (s & 3) * GRSTG;
        const uint32_t* bs2 = as + 128 * 20;
        #pragma unroll
        for (int ks = 0; ks < 2; ks++) {
            const int kk = ks * 8;
            uint4 a4[4];
            #pragma unroll
            for (int mf = 0; mf < 4; mf++) {
                int row = mb + mf * 16 + g4;
                a4[mf].x = as[row * 20 + kk + t4];
                a4[mf].y = as[(row + 8) * 20 + kk + t4];
                a4[mf].z = as[row * 20 + kk + 4 + t4];
                a4[mf].w = as[(row + 8) * 20 + kk + 4 + t4];
            }
            uint32_t bb[4][2];
            #pragma unroll
            for (int nf = 0; nf < 4; nf++) {
                int col = nb + nf * 8 + g4;
                bb[nf][0] = bs2[col * 20 + kk + t4];
                bb[nf][1] = bs2[col * 20 + kk + 4 + t4];
            }
            #pragma unroll
            for (int mf = 0; mf < 4; mf++)
                #pragma unroll
                for (int nf = 0; nf < 4; nf++)
                    MMA_TF32(acc[mf][nf], a4[mf], bb[nf][0], bb[nf][1]);
        }
    }

    float* gp = g_gp + ((size_t)(ksp * BATCH + b) * 10 + ti) * 16384;
    #pragma unroll
    for (int mf = 0; mf < 4; mf++) {
        #pragma unroll
        for (int nf = 0; nf < 4; nf++) {
            int row = mb + mf * 16 + g4;
            int col = nb + nf * 8 + t4 * 2;
            *(float2*)(gp + row * 128 + col)       = make_float2(acc[mf][nf][0], acc[mf][nf][1]);
            *(float2*)(gp + (row + 8) * 128 + col) = make_float2(acc[mf][nf][2], acc[mf][nf][3]);
        }
    }
}

// ---------------- K3b: reduce partials -> G, coalesced mirror via smem -----
__global__ __launch_bounds__(256) void greduce_kernel()
{
    int blk = blockIdx.x;            // b*20 + ti*2 + half
    int b = blk / 20, rem = blk % 20;
    int ti = rem >> 1, half = rem & 1;
    const int m0 = TRI_I[ti] * 128, n0 = TRI_J[ti] * 128;
    const bool mir = (m0 != n0);
    const int rbase = half * 64;
    uint32_t* Gb = g_G + (size_t)b * GSQ;
    int tid = threadIdx.x;

    __shared__ uint32_t ts[64][133];

    const float* gp0 = g_gp + ((size_t)b * 10 + ti) * 16384 + rbase * 128;
    const float* gp1 = g_gp + ((size_t)(BATCH + b) * 10 + ti) * 16384 + rbase * 128;

    #pragma unroll 4
    for (int i = 0; i < 32; i++) {
        int e = tid + i * 256;           // 0..8191
        float s = gp0[e] + gp1[e];
        uint32_t v = f2t(s);
        int row = e >> 7, col = e & 127;
        ts[row][col] = v;
        Gb[(size_t)(m0 + rbase + row) * CCH + n0 + col] = v;
    }
    if (mir) {
        __syncthreads();
        #pragma unroll 4
        for (int i = 0; i < 32; i++) {
            int idx = tid + i * 256;
            int c = idx >> 6, r = idx & 63;
            Gb[(size_t)(n0 + c) * CCH + m0 + rbase + r] = ts[r][c];
        }
    }
}

// ---------------- K4: generic tf32 GEMM (XNORM: inline GN from x) ----------
#define BK    16
#define WSTG  2560
#define XSTG  (BK * 136)
#define STGW  (WSTG + XSTG)
#define GSMEM  (4 * STGW * 4)
#define GSMEMX (4 * STGW * 4 + 4096)

template<int RES, int BMODE, int XNORM>
__global__ __launch_bounds__(256, 2) void gemm_mma(
    const uint32_t* __restrict__ Xsrc, int NN,
    const uint32_t* __restrict__ Wblob, size_t wbstride,
    const float* __restrict__ bias,
    const float* __restrict__ res,
    float* __restrict__ Out)
{
    extern __shared__ uint32_t sm[];
    const int tid = threadIdx.x, lane = tid & 31, wid = tid >> 5;
    const int b = blockIdx.z, n0 = blockIdx.x * 128, o0 = blockIdx.y * 128;
    const int m64g = o0 >> 6;
    const uint32_t* Xp = Xsrc + (size_t)b * CCH * NN;
    const float*    xf = (const float*)Xsrc + (size_t)b * CCH * NN;
    const uint32_t* Wb = Wblob + (size_t)b * wbstride;
    const uint32_t smb = sptr(sm);
    const int wm = wid >> 2, wn = wid & 3;
    const int mb = wm * 64, nb = wn * 32;
    const int g4 = lane >> 2, t4 = lane & 3;

    float* scs = (float*)(sm + 4 * STGW);
    float* bss = scs + 512;
    if (XNORM) {
        #pragma unroll
        for (int i = 0; i < 2; i++) {
            scs[tid + i * 256] = g_sc[b * CCH + tid + i * 256];
            bss[tid + i * 256] = g_bs[b * CCH + tid + i * 256];
        }
        __syncthreads();
    }

    auto issueW = [&](int s) {
        const int slot = s & 3;
        const uint32_t wd = smb + (uint32_t)slot * STGW * 4;
        const uint32_t* src0 = Wb + ((size_t)m64g * 64 + 2 * s) * 640;
        const uint32_t* src1 = Wb + ((size_t)(m64g + 1) * 64 + 2 * s) * 640;
        int c = tid;
        cpa16(wd + c * 16, src0 + c * 4);
        c = tid + 256;
        cpa16(wd + c * 16, c < 320 ? src0 + c * 4 : src1 + (c - 320) * 4);
        if (tid < 128) { c = tid + 512; cpa16(wd + c * 16, src1 + (c - 320) * 4); }
    };
    auto issueX = [&](int s) {
        const int slot = s & 3;
        const uint32_t xd = smb + (uint32_t)slot * STGW * 4 + WSTG * 4;
        const int k0 = s * BK;
        int r = tid >> 5, col = tid & 31;
        cpa16(xd + (uint32_t)(r * 136 + col * 4) * 4,
              Xp + (size_t)(k0 + r) * NN + n0 + col * 4);
        cpa16(xd + (uint32_t)((r + 8) * 136 + col * 4) * 4,
              Xp + (size_t)(k0 + r + 8) * NN + n0 + col * 4);
    };
    // XNORM register path
    float4 rx0, rx1;
    const int xr = tid >> 5, xc = tid & 31;
    auto ldgX = [&](int s) {
        const int k0 = s * BK;
        rx0 = *(const float4*)(xf + (size_t)(k0 + xr) * NN + n0 + xc * 4);
        rx1 = *(const float4*)(xf + (size_t)(k0 + xr + 8) * NN + n0 + xc * 4);
    };
    auto stsX = [&](int s) {
        const int slot = s & 3;
        uint32_t* xs = sm + slot * STGW + WSTG;
        const int k0 = s * BK;
        float s0 = scs[k0 + xr], b0 = bss[k0 + xr];
        float s1 = scs[k0 + xr + 8], b1 = bss[k0 + xr + 8];
        uint4 u0 = make_uint4(f2t(fmaf(rx0.x, s0, b0)), f2t(fmaf(rx0.y, s0, b0)),
                              f2t(fmaf(rx0.z, s0, b0)), f2t(fmaf(rx0.w, s0, b0)));
        uint4 u1 = make_uint4(f2t(fmaf(rx1.x, s1, b1)), f2t(fmaf(rx1.y, s1, b1)),
                              f2t(fmaf(rx1.z, s1, b1)), f2t(fmaf(rx1.w, s1, b1)));
        *(uint4*)(xs + xr * 136 + xc * 4) = u0;
        *(uint4*)(xs + (xr + 8) * 136 + xc * 4) = u1;
    };

    float acc[4][4][4];
    #pragma unroll
    for (int i = 0; i < 4; i++)
        #pragma unroll
        for (int j = 0; j < 4; j++)
            #pragma unroll
            for (int r = 0; r < 4; r++) acc[i][j][r] = 0.f;

    // prologue
    issueW(0); if (!XNORM) issueX(0); cpa_commit();
    issueW(1); if (!XNORM) issueX(1); cpa_commit();
    if (XNORM) { ldgX(0); stsX(0); ldgX(1); stsX(1); }

    const int NS = CCH / BK;   // 32
    #pragma unroll 1
    for (int s = 0; s < NS; s++) {
        if (s + 2 < NS) {
            issueW(s + 2); if (!XNORM) issueX(s + 2); cpa_commit();
            if (XNORM) ldgX(s + 2);
        } else cpa_commit();
        cpa_wait2();
        __syncthreads();
        if (XNORM && s + 2 < NS) stsX(s + 2);

        const uint32_t* ws = sm + (s & 3) * STGW;
        const uint32_t* xs = ws + WSTG;
        #pragma unroll
        for (int ks = 0; ks < 2; ks++) {
            uint4 a4[4];
            const uint32_t* wbase = ws + wm * 1280 + ks * 640 + lane * 20;
            #pragma unroll
            for (int mf = 0; mf < 4; mf++)
                a4[mf] = *(const uint4*)(wbase + mf * 4);
            uint32_t bb[4][2];
            const uint32_t* x0 = xs + (ks * 8 + t4) * 136 + nb + g4;
            #pragma unroll
            for (int nf = 0; nf < 4; nf++) {
                bb[nf][0] = x0[nf * 8];
                bb[nf][1] = x0[4 * 136 + nf * 8];
            }
            #pragma unroll
            for (int mf = 0; mf < 4; mf++)
                #pragma unroll
                for (int nf = 0; nf < 4; nf++)
                    MMA_TF32(acc[mf][nf], a4[mf], bb[nf][0], bb[nf][1]);
        }
    }

    #pragma unroll
    for (int mf = 0; mf < 4; mf++) {
        int row = o0 + mb + mf * 16 + g4;
        float bv0 = 0.f, bv1 = 0.f;
        if (BMODE) { bv0 = bias[b * CCH + row]; bv1 = bias[b * CCH + row + 8]; }
        #pragma unroll
        for (int nf = 0; nf < 4; nf++) {
            int col = n0 + nb + nf * 8 + t4 * 2;
            size_t a0 = ((size_t)b * CCH + row)     * NN + col;
            size_t a1 = ((size_t)b * CCH + row + 8) * NN + col;
            float2 v0 = { acc[mf][nf][0] + bv0, acc[mf][nf][1] + bv0 };
            float2 v1 = { acc[mf][nf][2] + bv1, acc[mf][nf][3] + bv1 };
            if (RES) {
                float2 r0 = *(const float2*)(res + a0);
                float2 r1 = *(const float2*)(res + a1);
                v0.x += r0.x; v0.y += r0.y;
                v1.x += r1.x; v1.y += r1.y;
            }
            *(float2*)(Out + a0) = v0;
            *(float2*)(Out + a1) = v1;
        }
    }
}

// ---------------- K5: rqk = W_{q,k} @ r ----------------
__global__ __launch_bounds__(256) void rqk_kernel(const float* __restrict__ wqkv)
{
    int b = blockIdx.x, tid = threadIdx.x;
    __shared__ float rsh[CCH];
    for (int i = tid; i < CCH; i += 256) rsh[i] = g_r[b * CCH + i];
    __syncthreads();
    for (int oo = tid; oo < 1024; oo += 256) {
        const float* wr = wqkv + (size_t)oo * CCH;
        float s = 0.f;
        for (int c = 0; c < CCH; c += 4) {
            float4 w = *(const float4*)(wr + c);
            s += w.x * rsh[c] + w.y * rsh[c+1] + w.z * rsh[c+2] + w.w * rsh[c+3];
        }
        g_rqk[b * 1024 + oo] = s;
    }
}

// ---------------- K6a: S split-K partials ----------------
__global__ __launch_bounds__(256) void sqk_kernel(const float* __restrict__ wqkv)
{
    int blk = blockIdx.x;
    int bh = blk >> 2, ksp = blk & 3;
    int b = bh >> 3, h = bh & 7;
    const float* Tq = g_T + ((size_t)b * CCH + h * HD) * CCH;
    const float* Wk = wqkv + (size_t)(CCH + h * HD) * CCH;
    __shared__ float qs[32][64], ks[32][64];
    int tid = threadIdx.x, ty = tid >> 4, tx = tid & 15;
    float acc[4][4] = {};
    const int kbeg = ksp * 128;
    for (int k0 = kbeg; k0 < kbeg + 128; k0 += 32) {
        #pragma unroll
        for (int i = 0; i < 2; i++) {
            int idx = tid + i * 256;
            int c = idx >> 3, q8 = idx & 7;
            float4 vq = *(const float4*)(Tq + (size_t)c * CCH + k0 + q8 * 4);
            float4 vk = *(const float4*)(Wk + (size_t)c * CCH + k0 + q8 * 4);
            int col = (((c >> 2) ^ q8) << 2) | (c & 3);
            int rr = q8 * 4;
            qs[rr+0][col] = vq.x; qs[rr+1][col] = vq.y; qs[rr+2][col] = vq.z; qs[rr+3][col] = vq.w;
            ks[rr+0][col] = vk.x; ks[rr+1][col] = vk.y; ks[rr+2][col] = vk.z; ks[rr+3][col] = vk.w;
        }
        __syncthreads();
        #pragma unroll
        for (int kk = 0; kk < 32; kk++) {
            int sw = (kk >> 2) & 7;
            float4 rq = *(const float4*)&qs[kk][(ty ^ sw) << 2];
            float4 rk = *(const float4*)&ks[kk][(tx ^ sw) << 2];
            float rqa[4] = {rq.x, rq.y, rq.z, rq.w};
            float rka[4] = {rk.x, rk.y, rk.z, rk.w};
            #pragma unroll
            for (int i = 0; i < 4; i++)
                #pragma unroll
                for (int j = 0; j < 4; j++)
                    acc[i][j] = fmaf(rqa[i], rka[j], acc[i][j]);
        }
        __syncthreads();
    }
    float* sp = g_ssp + (size_t)blk * (HD * HD);
    #pragma unroll
    for (int i = 0; i < 4; i++) {
        float4 v = { acc[i][0], acc[i][1], acc[i][2], acc[i][3] };
        *(float4*)(sp + (ty * 4 + i) * HD + tx * 4) = v;
    }
}

// ---------------- K6b: combine + rank-1 bias + softmax -> P ----------------
__global__ __launch_bounds__(64) void ssm_kernel(const float* __restrict__ bqkv)
{
    int bh = blockIdx.x, b = bh >> 3, h = bh & 7;
    int r = threadIdx.x;
    __shared__ float bks[64], rks[64];
    bks[r] = bqkv[CCH + h * HD + r];
    rks[r] = g_rqk[b * 1024 + CCH + h * HD + r];
    __syncthreads();
    float bq = bqkv[h * HD + r];
    float rq = g_rqk[b * 1024 + h * HD + r];

    float4 a[16];
    #pragma unroll
    for (int j = 0; j < 16; j++) a[j] = make_float4(0.f, 0.f, 0.f, 0.f);
    #pragma unroll
    for (int ksp = 0; ksp < 4; ksp++) {
        const float4* p = (const float4*)(g_ssp + ((size_t)bh * 4 + ksp) * (HD * HD) + r * HD);
        #pragma unroll
        for (int j = 0; j < 16; j++) {
            float4 v = p[j];
            a[j].x += v.x; a[j].y += v.y; a[j].z += v.z; a[j].w += v.w;
        }
    }
    float mx = -1e30f;
    #pragma unroll
    for (int j = 0; j < 16; j++) {
        int d = j * 4;
        a[j].x = (a[j].x + bq * rks[d]   + bks[d]   * rq + 4096.f * bq * bks[d]  ) * 0.125f;
        a[j].y = (a[j].y + bq * rks[d+1] + bks[d+1] * rq + 4096.f * bq * bks[d+1]) * 0.125f;
        a[j].z = (a[j].z + bq * rks[d+2] + bks[d+2] * rq + 4096.f * bq * bks[d+2]) * 0.125f;
        a[j].w = (a[j].w + bq * rks[d+3] + bks[d+3] * rq + 4096.f * bq * bks[d+3]) * 0.125f;
        mx = fmaxf(mx, fmaxf(fmaxf(a[j].x, a[j].y), fmaxf(a[j].z, a[j].w)));
    }
    float sum = 0.f;
    #pragma unroll
    for (int j = 0; j < 16; j++) {
        a[j].x = __expf(a[j].x - mx); a[j].y = __expf(a[j].y - mx);
        a[j].z = __expf(a[j].z - mx); a[j].w = __expf(a[j].w - mx);
        sum += a[j].x + a[j].y + a[j].z + a[j].w;
    }
    float inv = 1.f / sum;
    float4* po = (float4*)(g_Pm + (size_t)bh * (HD * HD) + r * HD);
    #pragma unroll
    for (int j = 0; j < 16; j++) {
        a[j].x *= inv; a[j].y *= inv; a[j].z *= inv; a[j].w *= inv;
        po[j] = a[j];
    }
}

// ---------------- K7: V1 = P Wv (split over 128-col chunks), pvec ----------
__global__ __launch_bounds__(256) void v1_kernel(
    const float* __restrict__ wqkv, const float* __restrict__ bqkv)
{
    int blk = blockIdx.x, bh = blk >> 2, kp = blk & 3;
    int b = bh >> 3, h = bh & 7;
    const float* Pm = g_Pm + (size_t)bh * HD * HD;
    const float* Wv = wqkv + (size_t)(2 * CCH + h * HD) * CCH;
    __shared__ float Ps[64][65];
    __shared__ float Ws[64][132];
    int tid = threadIdx.x, ty = tid >> 4, tx = tid & 15;
    #pragma unroll
    for (int i = 0; i < 4; i++) {
        int idx = tid + i * 256;
        int c = idx >> 4, q = idx & 15;
        float4 v = *(const float4*)(Pm + c * HD + q * 4);
        Ps[c][q*4] = v.x; Ps[c][q*4+1] = v.y; Ps[c][q*4+2] = v.z; Ps[c][q*4+3] = v.w;
    }
    #pragma unroll
    for (int i = 0; i < 8; i++) {
        int idx = tid + i * 256;
        int d = idx >> 5, q = idx & 31;
        float4 v = *(const float4*)(Wv + (size_t)d * CCH + kp * 128 + q * 4);
        *(float4*)&Ws[d][q * 4] = v;
    }
    __syncthreads();
    if (kp == 0 && tid < 64) {
        float s = 0.f;
        #pragma unroll 8
        for (int d = 0; d < 64; d++) s += Ps[tid][d] * bqkv[2 * CCH + h * HD + d];
        g_pvec[b * CCH + h * HD + tid] = s;
    }
    float acc[4][8] = {};
    #pragma unroll 2
    for (int d = 0; d < 64; d++) {
        float p0 = Ps[ty*4][d], p1 = Ps[ty*4+1][d], p2 = Ps[ty*4+2][d], p3 = Ps[ty*4+3][d];
        float4 w0 = *(const float4*)&Ws[d][tx * 8];
        float4 w1 = *(const float4*)&Ws[d][tx * 8 + 4];
        float wv[8] = {w0.x, w0.y, w0.z, w0.w, w1.x, w1.y, w1.z, w1.w};
        #pragma unroll
        for (int j = 0; j < 8; j++) {
            acc[0][j] = fmaf(p0, wv[j], acc[0][j]);
            acc[1][j] = fmaf(p1, wv[j], acc[1][j]);
            acc[2][j] = fmaf(p2, wv[j], acc[2][j]);
            acc[3][j] = fmaf(p3, wv[j], acc[3][j]);
        }
    }
    uint32_t* V1b = g_V1 + ((size_t)b * CCH + h * HD) * CCH;
    #pragma unroll
    for (int i = 0; i < 4; i++) {
        int c = ty * 4 + i;
        uint4 u0 = make_uint4(f2t(acc[i][0]), f2t(acc[i][1]), f2t(acc[i][2]), f2t(acc[i][3]));
        uint4 u1 = make_uint4(f2t(acc[i][4]), f2t(acc[i][5]), f2t(acc[i][6]), f2t(acc[i][7]));
        uint32_t* dst = V1b + (size_t)c * CCH + kp * 128 + tx * 8;
        *(uint4*)dst = u0;
        *(uint4*)(dst + 4) = u1;
    }
}

// ---------------- K8: cvec = Wp pvec + bp ----------------
__global__ __launch_bounds__(256) void cvec_kernel(
    const float* __restrict__ wp, const float* __restrict__ bp)
{
    int b = blockIdx.x >> 1, half = blockIdx.x & 1, tid = threadIdx.x;
    __shared__ float pv[CCH];
    for (int i = tid; i < CCH; i += 256) pv[i] = g_pvec[b * CCH + i];
    __syncthreads();
    int o = half * 256 + tid;
    const float* wr = wp + (size_t)o * CCH;
    float s = bp[o];
    for (int c = 0; c < CCH; c += 4) {
        float4 w = *(const float4*)(wr + c);
        s += w.x * pv[c] + w.y * pv[c+1] + w.z * pv[c+2] + w.w * pv[c+3];
    }
    g_cvec[b * CCH + o] = s;
}

// ---------------- K9: M -> per-batch blob ----------------
__global__ __launch_bounds__(256) void mblob_kernel()
{
    int gid = blockIdx.x * 256 + threadIdx.x;   // 16*16384
    int b = gid >> 14, e = gid & 16383;
    const float* M = g_M + (size_t)b * GSQ;
    int lane = e & 31, k8 = (e >> 5) & 63, m64 = e >> 11;
    int t4 = lane & 3, g4 = lane >> 2;
    uint32_t out[16];
    #pragma unroll
    for (int w = 0; w < 16; w++) {
        int mf = w >> 2, j = w & 3;
        int kk = k8 * 8 + t4 + ((j >> 1) << 2);
        int oo = m64 * 64 + mf * 16 + g4 + ((j & 1) << 3);
        out[w] = f2t(M[(size_t)oo * CCH + kk]);
    }
    uint32_t* dst = g_mblob + (size_t)b * WBSZ + (size_t)e * 20;
    #pragma unroll
    for (int q = 0; q < 4; q++)
        *(uint4*)(dst + q * 4) = make_uint4(out[q*4], out[q*4+1], out[q*4+2], out[q*4+3]);
}

// ---------------- launch ----------------
extern "C" void kernel_launch(void* const* d_in, const int* in_sizes, int n_in,
                              void* d_out, int out_size)
{
    const float* x      = (const float*)d_in[0];
    const float* gamma  = (const float*)d_in[1];
    const float* beta   = (const float*)d_in[2];
    const float* w_qkv  = (const float*)d_in[3];
    const float* b_qkv  = (const float*)d_in[4];
    const float* w_proj = (const float*)d_in[5];
    const float* b_proj = (const float*)d_in[6];
    float* out = (float*)d_out;

    uint32_t *G_ptr, *V1_ptr, *wtq_ptr, *wtp_ptr, *mb_ptr;
    float *T_ptr, *M_ptr, *cv_ptr;
    cudaGetSymbolAddress((void**)&G_ptr,  g_G);
    cudaGetSymbolAddress((void**)&V1_ptr, g_V1);
    cudaGetSymbolAddress((void**)&wtq_ptr, g_wtq8);
    cudaGetSymbolAddress((void**)&wtp_ptr, g_wtp);
    cudaGetSymbolAddress((void**)&mb_ptr, g_mblob);
    cudaGetSymbolAddress((void**)&T_ptr, g_T);
    cudaGetSymbolAddress((void**)&M_ptr, g_M);
    cudaGetSymbolAddress((void**)&cv_ptr, g_cvec);

    cudaFuncSetAttribute((const void*)gram_kernel,
                         cudaFuncAttributeMaxDynamicSharedMemorySize, GRSMEM);
    cudaFuncSetAttribute((const void*)gemm_mma<0, 0, 0>,
                         cudaFuncAttributeMaxDynamicSharedMemorySize, GSMEM);
    cudaFuncSetAttribute((const void*)gemm_mma<1, 1, 1>,
                         cudaFuncAttributeMaxDynamicSharedMemorySize, GSMEMX);

    wt_kernel<<<128, 256>>>(w_qkv, w_proj);
    gn_kernel<<<BATCH * NGRP, 256>>>(x, gamma, beta);

    // G = xn xn^T  (10 triangle tiles x 16 batches x 2 K-splits) + reduce
    {
        dim3 grid(10, BATCH, KSPL);
        gram_kernel<<<grid, 256, GRSMEM>>>();
        greduce_kernel<<<BATCH * 20, 256>>>();
    }
    // T = Wq @ G
    {
        dim3 grid(4, 4, BATCH);
        gemm_mma<0, 0, 0><<<grid, 256, GSMEM>>>(G_ptr, CCH, wtq_ptr, 0, nullptr, nullptr, T_ptr);
    }
    rqk_kernel<<<BATCH, 256>>>(w_qkv);
    sqk_kernel<<<BATCH * NH * 4, 256>>>(w_qkv);
    ssm_kernel<<<BATCH * NH, 64>>>(b_qkv);
    v1_kernel<<<BATCH * NH * 4, 256>>>(w_qkv, b_qkv);
    cvec_kernel<<<32, 256>>>(w_proj, b_proj);
    // M = Wp @ V1
    {
        dim3 grid(4, 4, BATCH);
        gemm_mma<0, 0, 0><<<grid, 256, GSMEM>>>(V1_ptr, CCH, wtp_ptr, 0, nullptr, nullptr, M_ptr);
    }
    mblob_kernel<<<1024, 256>>>();
    // out = M @ GN(x) + cvec + x   (GN fused inline; x read once, residual hits L2)
    {
        dim3 grid(HW / 128, 4, BATCH);
        gemm_mma<1, 1, 1><<<grid, 256, GSMEMX>>>((const uint32_t*)x, HW, mb_ptr, WBSZ, cv_ptr, x, out);
    }
}

// round 14
// speedup vs baseline: 1.1098x; 1.1098x over previous
#include <cuda_runtime.h>
#include <cstdint>

#define BATCH 16
#define CCH   512
#define HW    4096
#define NGRP  32
#define CPG   16
#define NH    8
#define HD    64
#define EPSV  1e-5f
#define WBSZ  (8 * 64 * 32 * 20)     // 512-row weight blob words
#define GSQ   (CCH * CCH)            // 262144
#define KSPL  4                      // gram split-K

// ---------------- scratch ----------------
__device__ uint32_t g_xn  [(size_t)BATCH * CCH * HW];   // tf32 bits [b][c][n]
__device__ uint32_t g_G   [(size_t)BATCH * GSQ];        // Gram tf32 [b][c1][c2]
__device__ float    g_gp  [(size_t)KSPL * BATCH * 10 * 16384]; // gram split-K partials
__device__ float    g_T   [(size_t)BATCH * GSQ];        // Wq@G fp32 [b][o][c2]
__device__ uint32_t g_V1  [(size_t)BATCH * GSQ];        // P·Wv tf32 [b][c1][k]
__device__ float    g_M   [(size_t)BATCH * GSQ];        // Wp@V1 fp32
__device__ uint32_t g_mblob[(size_t)BATCH * WBSZ];
__device__ uint32_t g_wtq8[WBSZ];                       // Wq blob (w_qkv rows 0..511)
__device__ uint32_t g_wtp [WBSZ];                       // Wp blob
__device__ float g_r  [BATCH * CCH];                    // xn row sums
__device__ float g_rqk[BATCH * 1024];                   // W_{q,k} @ r
__device__ float g_ssp[(size_t)BATCH * NH * 4 * HD * HD]; // S split-K partials
__device__ float g_Pm [(size_t)BATCH * NH * HD * HD];   // softmaxed P
__device__ float g_pvec[BATCH * CCH];
__device__ float g_cvec[BATCH * CCH];

// ---------------- helpers ----------------
__device__ __forceinline__ uint32_t f2t(float f) {
    uint32_t u; asm("cvt.rna.tf32.f32 %0, %1;" : "=r"(u) : "f"(f)); return u;
}
__device__ __forceinline__ uint32_t sptr(const void* p) {
    uint32_t a;
    asm("{ .reg .u64 t; cvta.to.shared.u64 t, %1; cvt.u32.u64 %0, t; }" : "=r"(a) : "l"(p));
    return a;
}
__device__ __forceinline__ void cpa16(uint32_t dst, const void* src) {
    asm volatile("cp.async.cg.shared.global [%0], [%1], 16;" :: "r"(dst), "l"(src));
}
__device__ __forceinline__ void cpa_commit() { asm volatile("cp.async.commit_group;" ::: "memory"); }
__device__ __forceinline__ void cpa_wait2()  { asm volatile("cp.async.wait_group 2;" ::: "memory"); }
#define MMA_TF32(acc, a4, b0, b1) \
    asm volatile("mma.sync.aligned.m16n8k8.row.col.f32.tf32.tf32.f32 " \
        "{%0,%1,%2,%3}, {%4,%5,%6,%7}, {%8,%9}, {%0,%1,%2,%3};" \
        : "+f"((acc)[0]), "+f"((acc)[1]), "+f"((acc)[2]), "+f"((acc)[3]) \
        : "r"((a4).x), "r"((a4).y), "r"((a4).z), "r"((a4).w), "r"(b0), "r"(b1))

// ---------------- K0: weight blobs ----------------
__global__ __launch_bounds__(256) void wt_kernel(
    const float* __restrict__ Wq, const float* __restrict__ Wp)
{
    int idx = blockIdx.x * 256 + threadIdx.x;   // 32768
    const float* W; uint32_t* blob; int e;
    if (idx < 16384) { W = Wq; blob = g_wtq8; e = idx; }
    else             { W = Wp; blob = g_wtp;  e = idx - 16384; }
    int lane = e & 31, k8 = (e >> 5) & 63, m64 = e >> 11;
    int t4 = lane & 3, g4 = lane >> 2;
    uint32_t out[16];
    #pragma unroll
    for (int w = 0; w < 16; w++) {
        int mf = w >> 2, j = w & 3;
        int kk = k8 * 8 + t4 + ((j >> 1) << 2);
        int oo = m64 * 64 + mf * 16 + g4 + ((j & 1) << 3);
        out[w] = f2t(W[(size_t)oo * CCH + kk]);
    }
    uint32_t* dst = blob + (size_t)e * 20;
    #pragma unroll
    for (int q = 0; q < 4; q++)
        *(uint4*)(dst + q * 4) = make_uint4(out[q*4], out[q*4+1], out[q*4+2], out[q*4+3]);
}

// ---------------- K1: GroupNorm FUSED: stats + normalize + row sums --------
__global__ __launch_bounds__(256) void gn_kernel(
    const float* __restrict__ x, const float* __restrict__ gamma,
    const float* __restrict__ beta)
{
    int bg = blockIdx.x;
    int b = bg / NGRP, g = bg % NGRP;
    const float* xp = x + ((size_t)b * CCH + (size_t)g * CPG) * HW;
    int tid = threadIdx.x;
    int warp = tid >> 5, lane = tid & 31;

    float s = 0.f, ss = 0.f;
    const float4* xp4 = (const float4*)xp;
    for (int i = tid; i < (CPG * HW) / 4; i += 256) {
        float4 v = xp4[i];
        s  += v.x + v.y + v.z + v.w;
        ss += v.x*v.x + v.y*v.y + v.z*v.z + v.w*v.w;
    }
    __shared__ float sh_s[256], sh_ss[256];
    __shared__ float sc16[CPG], bs16[CPG];
    sh_s[tid] = s; sh_ss[tid] = ss;
    __syncthreads();
    for (int off = 128; off > 0; off >>= 1) {
        if (tid < off) { sh_s[tid] += sh_s[tid+off]; sh_ss[tid] += sh_ss[tid+off]; }
        __syncthreads();
    }
    if (tid < CPG) {
        const float inv_n = 1.0f / (float)(CPG * HW);
        float mean = sh_s[0] * inv_n;
        float var  = sh_ss[0] * inv_n - mean * mean;
        float inv  = rsqrtf(var + EPSV);
        int c = g * CPG + tid;
        float ga = gamma[c], be = beta[c];
        sc16[tid] = ga * inv;
        bs16[tid] = be - mean * inv * ga;
    }
    __syncthreads();

    #pragma unroll
    for (int half = 0; half < 2; half++) {
        int c = warp * 2 + half;
        float sc = sc16[c], bs = bs16[c];
        const float4* src = (const float4*)(xp + (size_t)c * HW);
        uint4* dst = (uint4*)(g_xn + ((size_t)(b * CCH + g * CPG + c)) * HW);
        float sum = 0.f;
        for (int i = lane; i < HW / 4; i += 32) {
            float4 v = src[i];
            uint4 u;
            u.x = f2t(fmaf(v.x, sc, bs));
            u.y = f2t(fmaf(v.y, sc, bs));
            u.z = f2t(fmaf(v.z, sc, bs));
            u.w = f2t(fmaf(v.w, sc, bs));
            dst[i] = u;
            sum += __uint_as_float(u.x) + __uint_as_float(u.y)
                 + __uint_as_float(u.z) + __uint_as_float(u.w);
        }
        #pragma unroll
        for (int off = 16; off > 0; off >>= 1)
            sum += __shfl_xor_sync(0xFFFFFFFF, sum, off);
        if (lane == 0)
            g_r[b * CCH + g * CPG + c] = sum;
    }
}

// ---------------- K3: Gram split-K partials (reads g_xn) ----------
__device__ const int TRI_I[10] = {0,1,1,2,2,2,3,3,3,3};
__device__ const int TRI_J[10] = {0,0,1,0,1,2,0,1,2,3};
#define GRSTG  (2 * 128 * 20)        // 5120 words per slot
#define GRSMEM (4 * GRSTG * 4)       // 81920 bytes

__global__ __launch_bounds__(256, 2) void gram_kernel()
{
    extern __shared__ uint32_t sm[];
    const int tid = threadIdx.x, lane = tid & 31, wid = tid >> 5;
    const int ti = blockIdx.x, b = blockIdx.y, ksp = blockIdx.z;
    const int m0 = TRI_I[ti] * 128, n0 = TRI_J[ti] * 128;
    const uint32_t* Xp = g_xn + (size_t)b * CCH * HW;
    const uint32_t smb = sptr(sm);
    const int wm = wid >> 2, wn = wid & 3;
    const int mb = wm * 64, nb = wn * 32;
    const int g4 = lane >> 2, t4 = lane & 3;
    const int kbase = ksp * (HW / KSPL);   // 1024

    auto issue = [&](int s) {
        const int slot = s & 3;
        const uint32_t ad = smb + (uint32_t)slot * GRSTG * 4;
        const uint32_t bd = ad + 128 * 20 * 4;
        const int k0 = kbase + s * 16;
        #pragma unroll
        for (int i = 0; i < 2; i++) {
            int ch = tid + i * 256;
            int row = ch >> 2, kq = ch & 3;
            cpa16(ad + (uint32_t)(row * 20 + kq * 4) * 4,
                  Xp + (size_t)(m0 + row) * HW + k0 + kq * 4);
            cpa16(bd + (uint32_t)(row * 20 + kq * 4) * 4,
                  Xp + (size_t)(n0 + row) * HW + k0 + kq * 4);
        }
        cpa_commit();
    };

    float acc[4][4][4];
    #pragma unroll
    for (int i = 0; i < 4; i++)
        #pragma unroll
        for (int j = 0; j < 4; j++)
            #pragma unroll
            for (int r = 0; r < 4; r++) acc[i][j][r] = 0.f;

    issue(0); issue(1);
    const int NS = (HW / KSPL) / 16;   // 64
    #pragma unroll 1
    for (int s = 0; s < NS; s++) {
        if (s + 2 < NS) issue(s + 2); else cpa_commit();
        cpa_wait2();
        __syncthreads();
        const uint32_t* as = sm + (s & 3) * GRSTG;
        const uint32_t* bs2 = as + 128 * 20;
        #pragma unroll
        for (int ks = 0; ks < 2; ks++) {
            const int kk = ks * 8;
            uint4 a4[4];
            #pragma unroll
            for (int mf = 0; mf < 4; mf++) {
                int row = mb + mf * 16 + g4;
                a4[mf].x = as[row * 20 + kk + t4];
                a4[mf].y = as[(row + 8) * 20 + kk + t4];
                a4[mf].z = as[row * 20 + kk + 4 + t4];
                a4[mf].w = as[(row + 8) * 20 + kk + 4 + t4];
            }
            uint32_t bb[4][2];
            #pragma unroll
            for (int nf = 0; nf < 4; nf++) {
                int col = nb + nf * 8 + g4;
                bb[nf][0] = bs2[col * 20 + kk + t4];
                bb[nf][1] = bs2[col * 20 + kk + 4 + t4];
            }
            #pragma unroll
            for (int mf = 0; mf < 4; mf++)
                #pragma unroll
                for (int nf = 0; nf < 4; nf++)
                    MMA_TF32(acc[mf][nf], a4[mf], bb[nf][0], bb[nf][1]);
        }
    }

    float* gp = g_gp + ((size_t)(ksp * BATCH + b) * 10 + ti) * 16384;
    #pragma unroll
    for (int mf = 0; mf < 4; mf++) {
        #pragma unroll
        for (int nf = 0; nf < 4; nf++) {
            int row = mb + mf * 16 + g4;
            int col = nb + nf * 8 + t4 * 2;
            *(float2*)(gp + row * 128 + col)       = make_float2(acc[mf][nf][0], acc[mf][nf][1]);
            *(float2*)(gp + (row + 8) * 128 + col) = make_float2(acc[mf][nf][2], acc[mf][nf][3]);
        }
    }
}

// ---------------- K3b: reduce partials -> G, coalesced mirror via smem -----
__global__ __launch_bounds__(256) void greduce_kernel()
{
    int blk = blockIdx.x;            // b*20 + ti*2 + half
    int b = blk / 20, rem = blk % 20;
    int ti = rem >> 1, half = rem & 1;
    const int m0 = TRI_I[ti] * 128, n0 = TRI_J[ti] * 128;
    const bool mir = (m0 != n0);
    const int rbase = half * 64;
    uint32_t* Gb = g_G + (size_t)b * GSQ;
    int tid = threadIdx.x;

    __shared__ uint32_t ts[64][133];

    #pragma unroll 4
    for (int i = 0; i < 32; i++) {
        int e = tid + i * 256;           // 0..8191
        float s = 0.f;
        #pragma unroll
        for (int ksp = 0; ksp < KSPL; ksp++)
            s += g_gp[((size_t)(ksp * BATCH + b) * 10 + ti) * 16384 + rbase * 128 + e];
        uint32_t v = f2t(s);
        int row = e >> 7, col = e & 127;
        ts[row][col] = v;
        Gb[(size_t)(m0 + rbase + row) * CCH + n0 + col] = v;
    }
    if (mir) {
        __syncthreads();
        #pragma unroll 4
        for (int i = 0; i < 32; i++) {
            int idx = tid + i * 256;
            int c = idx >> 6, r = idx & 63;
            Gb[(size_t)(n0 + c) * CCH + m0 + rbase + r] = ts[r][c];
        }
    }
}

// ---------------- K4: generic tf32 GEMM (r8 template) ----------------
#define BK    16
#define WSTG  2560
#define XSTG  (BK * 136)
#define STGW  (WSTG + XSTG)
#define GSMEM (4 * STGW * 4)

template<int RES, int BMODE>
__global__ __launch_bounds__(256, 2) void gemm_mma(
    const uint32_t* __restrict__ Xsrc, int NN,
    const uint32_t* __restrict__ Wblob, size_t wbstride,
    const float* __restrict__ bias,
    const float* __restrict__ res,
    float* __restrict__ Out)
{
    extern __shared__ uint32_t sm[];
    const int tid = threadIdx.x, lane = tid & 31, wid = tid >> 5;
    const int b = blockIdx.z, n0 = blockIdx.x * 128, o0 = blockIdx.y * 128;
    const int m64g = o0 >> 6;
    const uint32_t* Xp = Xsrc + (size_t)b * CCH * NN;
    const uint32_t* Wb = Wblob + (size_t)b * wbstride;
    const uint32_t smb = sptr(sm);
    const int wm = wid >> 2, wn = wid & 3;
    const int mb = wm * 64, nb = wn * 32;
    const int g4 = lane >> 2, t4 = lane & 3;

    auto issue = [&](int s) {
        const int slot = s & 3;
        const uint32_t wd = smb + (uint32_t)slot * STGW * 4;
        const uint32_t xd = wd + WSTG * 4;
        const uint32_t* src0 = Wb + ((size_t)m64g * 64 + 2 * s) * 640;
        const uint32_t* src1 = Wb + ((size_t)(m64g + 1) * 64 + 2 * s) * 640;
        {
            int c = tid;
            cpa16(wd + c * 16, src0 + c * 4);
            c = tid + 256;
            cpa16(wd + c * 16, c < 320 ? src0 + c * 4 : src1 + (c - 320) * 4);
            if (tid < 128) { c = tid + 512; cpa16(wd + c * 16, src1 + (c - 320) * 4); }
        }
        {
            const int k0 = s * BK;
            int r = tid >> 5, col = tid & 31;
            cpa16(xd + (uint32_t)(r * 136 + col * 4) * 4,
                  Xp + (size_t)(k0 + r) * NN + n0 + col * 4);
            int c2 = tid + 256;
            r = c2 >> 5; col = c2 & 31;
            cpa16(xd + (uint32_t)(r * 136 + col * 4) * 4,
                  Xp + (size_t)(k0 + r) * NN + n0 + col * 4);
        }
        cpa_commit();
    };

    float acc[4][4][4];
    #pragma unroll
    for (int i = 0; i < 4; i++)
        #pragma unroll
        for (int j = 0; j < 4; j++)
            #pragma unroll
            for (int r = 0; r < 4; r++) acc[i][j][r] = 0.f;

    issue(0); issue(1);
    const int NS = CCH / BK;   // 32
    #pragma unroll 1
    for (int s = 0; s < NS; s++) {
        if (s + 2 < NS) issue(s + 2); else cpa_commit();
        cpa_wait2();
        __syncthreads();
        const uint32_t* ws = sm + (s & 3) * STGW;
        const uint32_t* xs = ws + WSTG;
        #pragma unroll
        for (int ks = 0; ks < 2; ks++) {
            uint4 a4[4];
            const uint32_t* wbase = ws + wm * 1280 + ks * 640 + lane * 20;
            #pragma unroll
            for (int mf = 0; mf < 4; mf++)
                a4[mf] = *(const uint4*)(wbase + mf * 4);
            uint32_t bb[4][2];
            const uint32_t* x0 = xs + (ks * 8 + t4) * 136 + nb + g4;
            #pragma unroll
            for (int nf = 0; nf < 4; nf++) {
                bb[nf][0] = x0[nf * 8];
                bb[nf][1] = x0[4 * 136 + nf * 8];
            }
            #pragma unroll
            for (int mf = 0; mf < 4; mf++)
                #pragma unroll
                for (int nf = 0; nf < 4; nf++)
                    MMA_TF32(acc[mf][nf], a4[mf], bb[nf][0], bb[nf][1]);
        }
    }

    #pragma unroll
    for (int mf = 0; mf < 4; mf++) {
        int row = o0 + mb + mf * 16 + g4;
        float bv0 = 0.f, bv1 = 0.f;
        if (BMODE) { bv0 = bias[b * CCH + row]; bv1 = bias[b * CCH + row + 8]; }
        #pragma unroll
        for (int nf = 0; nf < 4; nf++) {
            int col = n0 + nb + nf * 8 + t4 * 2;
            size_t a0 = ((size_t)b * CCH + row)     * NN + col;
            size_t a1 = ((size_t)b * CCH + row + 8) * NN + col;
            float2 v0 = { acc[mf][nf][0] + bv0, acc[mf][nf][1] + bv0 };
            float2 v1 = { acc[mf][nf][2] + bv1, acc[mf][nf][3] + bv1 };
            if (RES) {
                float2 r0 = *(const float2*)(res + a0);
                float2 r1 = *(const float2*)(res + a1);
                v0.x += r0.x; v0.y += r0.y;
                v1.x += r1.x; v1.y += r1.y;
            }
            *(float2*)(Out + a0) = v0;
            *(float2*)(Out + a1) = v1;
        }
    }
}

// ---------------- K5: rqk = W_{q,k} @ r ----------------
__global__ __launch_bounds__(256) void rqk_kernel(const float* __restrict__ wqkv)
{
    int b = blockIdx.x, tid = threadIdx.x;
    __shared__ float rsh[CCH];
    for (int i = tid; i < CCH; i += 256) rsh[i] = g_r[b * CCH + i];
    __syncthreads();
    for (int oo = tid; oo < 1024; oo += 256) {
        const float* wr = wqkv + (size_t)oo * CCH;
        float s = 0.f;
        for (int c = 0; c < CCH; c += 4) {
            float4 w = *(const float4*)(wr + c);
            s += w.x * rsh[c] + w.y * rsh[c+1] + w.z * rsh[c+2] + w.w * rsh[c+3];
        }
        g_rqk[b * 1024 + oo] = s;
    }
}

// ---------------- K6a: S split-K partials ----------------
__global__ __launch_bounds__(256) void sqk_kernel(const float* __restrict__ wqkv)
{
    int blk = blockIdx.x;
    int bh = blk >> 2, ksp = blk & 3;
    int b = bh >> 3, h = bh & 7;
    const float* Tq = g_T + ((size_t)b * CCH + h * HD) * CCH;
    const float* Wk = wqkv + (size_t)(CCH + h * HD) * CCH;
    __shared__ float qs[32][64], ks[32][64];
    int tid = threadIdx.x, ty = tid >> 4, tx = tid & 15;
    float acc[4][4] = {};
    const int kbeg = ksp * 128;
    for (int k0 = kbeg; k0 < kbeg + 128; k0 += 32) {
        #pragma unroll
        for (int i = 0; i < 2; i++) {
            int idx = tid + i * 256;
            int c = idx >> 3, q8 = idx & 7;
            float4 vq = *(const float4*)(Tq + (size_t)c * CCH + k0 + q8 * 4);
            float4 vk = *(const float4*)(Wk + (size_t)c * CCH + k0 + q8 * 4);
            int col = (((c >> 2) ^ q8) << 2) | (c & 3);
            int rr = q8 * 4;
            qs[rr+0][col] = vq.x; qs[rr+1][col] = vq.y; qs[rr+2][col] = vq.z; qs[rr+3][col] = vq.w;
            ks[rr+0][col] = vk.x; ks[rr+1][col] = vk.y; ks[rr+2][col] = vk.z; ks[rr+3][col] = vk.w;
        }
        __syncthreads();
        #pragma unroll
        for (int kk = 0; kk < 32; kk++) {
            int sw = (kk >> 2) & 7;
            float4 rq = *(const float4*)&qs[kk][(ty ^ sw) << 2];
            float4 rk = *(const float4*)&ks[kk][(tx ^ sw) << 2];
            float rqa[4] = {rq.x, rq.y, rq.z, rq.w};
            float rka[4] = {rk.x, rk.y, rk.z, rk.w};
            #pragma unroll
            for (int i = 0; i < 4; i++)
                #pragma unroll
                for (int j = 0; j < 4; j++)
                    acc[i][j] = fmaf(rqa[i], rka[j], acc[i][j]);
        }
        __syncthreads();
    }
    float* sp = g_ssp + (size_t)blk * (HD * HD);
    #pragma unroll
    for (int i = 0; i < 4; i++) {
        float4 v = { acc[i][0], acc[i][1], acc[i][2], acc[i][3] };
        *(float4*)(sp + (ty * 4 + i) * HD + tx * 4) = v;
    }
}

// ---------------- K6b: combine + rank-1 bias + softmax -> P ----------------
__global__ __launch_bounds__(64) void ssm_kernel(const float* __restrict__ bqkv)
{
    int bh = blockIdx.x, b = bh >> 3, h = bh & 7;
    int r = threadIdx.x;
    __shared__ float bks[64], rks[64];
    bks[r] = bqkv[CCH + h * HD + r];
    rks[r] = g_rqk[b * 1024 + CCH + h * HD + r];
    __syncthreads();
    float bq = bqkv[h * HD + r];
    float rq = g_rqk[b * 1024 + h * HD + r];

    float4 a[16];
    #pragma unroll
    for (int j = 0; j < 16; j++) a[j] = make_float4(0.f, 0.f, 0.f, 0.f);
    #pragma unroll
    for (int ksp = 0; ksp < 4; ksp++) {
        const float4* p = (const float4*)(g_ssp + ((size_t)bh * 4 + ksp) * (HD * HD) + r * HD);
        #pragma unroll
        for (int j = 0; j < 16; j++) {
            float4 v = p[j];
            a[j].x += v.x; a[j].y += v.y; a[j].z += v.z; a[j].w += v.w;
        }
    }
    float mx = -1e30f;
    #pragma unroll
    for (int j = 0; j < 16; j++) {
        int d = j * 4;
        a[j].x = (a[j].x + bq * rks[d]   + bks[d]   * rq + 4096.f * bq * bks[d]  ) * 0.125f;
        a[j].y = (a[j].y + bq * rks[d+1] + bks[d+1] * rq + 4096.f * bq * bks[d+1]) * 0.125f;
        a[j].z = (a[j].z + bq * rks[d+2] + bks[d+2] * rq + 4096.f * bq * bks[d+2]) * 0.125f;
        a[j].w = (a[j].w + bq * rks[d+3] + bks[d+3] * rq + 4096.f * bq * bks[d+3]) * 0.125f;
        mx = fmaxf(mx, fmaxf(fmaxf(a[j].x, a[j].y), fmaxf(a[j].z, a[j].w)));
    }
    float sum = 0.f;
    #pragma unroll
    for (int j = 0; j < 16; j++) {
        a[j].x = __expf(a[j].x - mx); a[j].y = __expf(a[j].y - mx);
        a[j].z = __expf(a[j].z - mx); a[j].w = __expf(a[j].w - mx);
        sum += a[j].x + a[j].y + a[j].z + a[j].w;
    }
    float inv = 1.f / sum;
    float4* po = (float4*)(g_Pm + (size_t)bh * (HD * HD) + r * HD);
    #pragma unroll
    for (int j = 0; j < 16; j++) {
        a[j].x *= inv; a[j].y *= inv; a[j].z *= inv; a[j].w *= inv;
        po[j] = a[j];
    }
}

// ---------------- K7: V1 = P Wv (split over 128-col chunks), pvec ----------
__global__ __launch_bounds__(256) void v1_kernel(
    const float* __restrict__ wqkv, const float* __restrict__ bqkv)
{
    int blk = blockIdx.x, bh = blk >> 2, kp = blk & 3;
    int b = bh >> 3, h = bh & 7;
    const float* Pm = g_Pm + (size_t)bh * HD * HD;
    const float* Wv = wqkv + (size_t)(2 * CCH + h * HD) * CCH;
    __shared__ float Ps[64][65];
    __shared__ float Ws[64][132];
    int tid = threadIdx.x, ty = tid >> 4, tx = tid & 15;
    #pragma unroll
    for (int i = 0; i < 4; i++) {
        int idx = tid + i * 256;
        int c = idx >> 4, q = idx & 15;
        float4 v = *(const float4*)(Pm + c * HD + q * 4);
        Ps[c][q*4] = v.x; Ps[c][q*4+1] = v.y; Ps[c][q*4+2] = v.z; Ps[c][q*4+3] = v.w;
    }
    #pragma unroll
    for (int i = 0; i < 8; i++) {
        int idx = tid + i * 256;
        int d = idx >> 5, q = idx & 31;
        float4 v = *(const float4*)(Wv + (size_t)d * CCH + kp * 128 + q * 4);
        *(float4*)&Ws[d][q * 4] = v;
    }
    __syncthreads();
    if (kp == 0 && tid < 64) {
        float s = 0.f;
        #pragma unroll 8
        for (int d = 0; d < 64; d++) s += Ps[tid][d] * bqkv[2 * CCH + h * HD + d];
        g_pvec[b * CCH + h * HD + tid] = s;
    }
    float acc[4][8] = {};
    #pragma unroll 2
    for (int d = 0; d < 64; d++) {
        float p0 = Ps[ty*4][d], p1 = Ps[ty*4+1][d], p2 = Ps[ty*4+2][d], p3 = Ps[ty*4+3][d];
        float4 w0 = *(const float4*)&Ws[d][tx * 8];
        float4 w1 = *(const float4*)&Ws[d][tx * 8 + 4];
        float wv[8] = {w0.x, w0.y, w0.z, w0.w, w1.x, w1.y, w1.z, w1.w};
        #pragma unroll
        for (int j = 0; j < 8; j++) {
            acc[0][j] = fmaf(p0, wv[j], acc[0][j]);
            acc[1][j] = fmaf(p1, wv[j], acc[1][j]);
            acc[2][j] = fmaf(p2, wv[j], acc[2][j]);
            acc[3][j] = fmaf(p3, wv[j], acc[3][j]);
        }
    }
    uint32_t* V1b = g_V1 + ((size_t)b * CCH + h * HD) * CCH;
    #pragma unroll
    for (int i = 0; i < 4; i++) {
        int c = ty * 4 + i;
        uint4 u0 = make_uint4(f2t(acc[i][0]), f2t(acc[i][1]), f2t(acc[i][2]), f2t(acc[i][3]));
        uint4 u1 = make_uint4(f2t(acc[i][4]), f2t(acc[i][5]), f2t(acc[i][6]), f2t(acc[i][7]));
        uint32_t* dst = V1b + (size_t)c * CCH + kp * 128 + tx * 8;
        *(uint4*)dst = u0;
        *(uint4*)(dst + 4) = u1;
    }
}

// ---------------- K8: cvec = Wp pvec + bp ----------------
__global__ __launch_bounds__(256) void cvec_kernel(
    const float* __restrict__ wp, const float* __restrict__ bp)
{
    int b = blockIdx.x >> 1, half = blockIdx.x & 1, tid = threadIdx.x;
    __shared__ float pv[CCH];
    for (int i = tid; i < CCH; i += 256) pv[i] = g_pvec[b * CCH + i];
    __syncthreads();
    int o = half * 256 + tid;
    const float* wr = wp + (size_t)o * CCH;
    float s = bp[o];
    for (int c = 0; c < CCH; c += 4) {
        float4 w = *(const float4*)(wr + c);
        s += w.x * pv[c] + w.y * pv[c+1] + w.z * pv[c+2] + w.w * pv[c+3];
    }
    g_cvec[b * CCH + o] = s;
}

// ---------------- K9: M -> per-batch blob ----------------
__global__ __launch_bounds__(256) void mblob_kernel()
{
    int gid = blockIdx.x * 256 + threadIdx.x;   // 16*16384
    int b = gid >> 14, e = gid & 16383;
    const float* M = g_M + (size_t)b * GSQ;
    int lane = e & 31, k8 = (e >> 5) & 63, m64 = e >> 11;
    int t4 = lane & 3, g4 = lane >> 2;
    uint32_t out[16];
    #pragma unroll
    for (int w = 0; w < 16; w++) {
        int mf = w >> 2, j = w & 3;
        int kk = k8 * 8 + t4 + ((j >> 1) << 2);
        int oo = m64 * 64 + mf * 16 + g4 + ((j & 1) << 3);
        out[w] = f2t(M[(size_t)oo * CCH + kk]);
    }
    uint32_t* dst = g_mblob + (size_t)b * WBSZ + (size_t)e * 20;
    #pragma unroll
    for (int q = 0; q < 4; q++)
        *(uint4*)(dst + q * 4) = make_uint4(out[q*4], out[q*4+1], out[q*4+2], out[q*4+3]);
}

// ---------------- launch ----------------
extern "C" void kernel_launch(void* const* d_in, const int* in_sizes, int n_in,
                              void* d_out, int out_size)
{
    const float* x      = (const float*)d_in[0];
    const float* gamma  = (const float*)d_in[1];
    const float* beta   = (const float*)d_in[2];
    const float* w_qkv  = (const float*)d_in[3];
    const float* b_qkv  = (const float*)d_in[4];
    const float* w_proj = (const float*)d_in[5];
    const float* b_proj = (const float*)d_in[6];
    float* out = (float*)d_out;

    uint32_t *xn_ptr, *G_ptr, *V1_ptr, *wtq_ptr, *wtp_ptr, *mb_ptr;
    float *T_ptr, *M_ptr, *cv_ptr;
    cudaGetSymbolAddress((void**)&xn_ptr, g_xn);
    cudaGetSymbolAddress((void**)&G_ptr,  g_G);
    cudaGetSymbolAddress((void**)&V1_ptr, g_V1);
    cudaGetSymbolAddress((void**)&wtq_ptr, g_wtq8);
    cudaGetSymbolAddress((void**)&wtp_ptr, g_wtp);
    cudaGetSymbolAddress((void**)&mb_ptr, g_mblob);
    cudaGetSymbolAddress((void**)&T_ptr, g_T);
    cudaGetSymbolAddress((void**)&M_ptr, g_M);
    cudaGetSymbolAddress((void**)&cv_ptr, g_cvec);

    cudaFuncSetAttribute((const void*)gram_kernel,
                         cudaFuncAttributeMaxDynamicSharedMemorySize, GRSMEM);
    cudaFuncSetAttribute((const void*)gemm_mma<0, 0>,
                         cudaFuncAttributeMaxDynamicSharedMemorySize, GSMEM);
    cudaFuncSetAttribute((const void*)gemm_mma<1, 1>,
                         cudaFuncAttributeMaxDynamicSharedMemorySize, GSMEM);

    wt_kernel<<<128, 256>>>(w_qkv, w_proj);
    gn_kernel<<<BATCH * NGRP, 256>>>(x, gamma, beta);

    // G = xn xn^T  (10 triangle tiles x 16 batches x 4 K-splits) + reduce
    {
        dim3 grid(10, BATCH, KSPL);
        gram_kernel<<<grid, 256, GRSMEM>>>();
        greduce_kernel<<<BATCH * 20, 256>>>();
    }
    // T = Wq @ G
    {
        dim3 grid(4, 4, BATCH);
        gemm_mma<0, 0><<<grid, 256, GSMEM>>>(G_ptr, CCH, wtq_ptr, 0, nullptr, nullptr, T_ptr);
    }
    rqk_kernel<<<BATCH, 256>>>(w_qkv);
    sqk_kernel<<<BATCH * NH * 4, 256>>>(w_qkv);
    ssm_kernel<<<BATCH * NH, 64>>>(b_qkv);
    v1_kernel<<<BATCH * NH * 4, 256>>>(w_qkv, b_qkv);
    cvec_kernel<<<32, 256>>>(w_proj, b_proj);
    // M = Wp @ V1
    {
        dim3 grid(4, 4, BATCH);
        gemm_mma<0, 0><<<grid, 256, GSMEM>>>(V1_ptr, CCH, wtp_ptr, 0, nullptr, nullptr, M_ptr);
    }
    mblob_kernel<<<1024, 256>>>();
    // out = M @ xn + cvec + x
    {
        dim3 grid(HW / 128, 4, BATCH);
        gemm_mma<1, 1><<<grid, 256, GSMEM>>>(xn_ptr, HW, mb_ptr, WBSZ, cv_ptr, x, out);
    }
}